// round 15
// baseline (speedup 1.0000x reference)
#include <cuda_runtime.h>
#include <cstdint>

// SceneContraction: means = contract(mean); cov_out = J cov J^T where ||mean||>=1 else cov.
// J = g*I + c*x x^T, g = inv*(2-inv), c = 2*inv^3*(inv-1), inv = 1/||x||.
//
// R14: warp-independent pipelines. Each warp owns 128 contiguous samples,
// stages them through smem purely for layout redistribution:
//   fill  : cp.async, 12 float4/lane, lane-stride (coalesced 6KB chunk)
//   comp  : thread-private LDS.128 at stride 3/9 f4 (conflict-free)
//   drain : STG.128 lane-stride (coalesced)
// Synchronization is __syncwarp only - no __syncthreads - so every warp on
// the SM advances through load/compute/store phases independently, keeping
// the memory queues continuously full.

#define THREADS 128
#define WARPS (THREADS / 32)
#define M4_PER_WARP 96    // 32 lanes * 3 float4 of mean
#define C4_PER_WARP 288   // 32 lanes * 9 float4 of cov
#define M4_PER_BLOCK (WARPS * M4_PER_WARP)
#define C4_PER_BLOCK (WARPS * C4_PER_WARP)

__device__ __forceinline__ void cpasync16(void* smem_dst, const void* gmem_src) {
    uint32_t d = (uint32_t)__cvta_generic_to_shared(smem_dst);
    asm volatile("cp.async.cg.shared.global [%0], [%1], 16;"
                 :: "r"(d), "l"(gmem_src) : "memory");
}

__global__ __launch_bounds__(THREADS)
void scene_contract_kernel(const float4* __restrict__ mean4,
                           const float4* __restrict__ cov4,
                           float4* __restrict__ mout4,
                           float4* __restrict__ cout4) {
    __shared__ float4 smean[M4_PER_BLOCK];  // 6 KB
    __shared__ float4 scov[C4_PER_BLOCK];   // 18 KB

    const int t = threadIdx.x;
    const int w = t >> 5;
    const int l = t & 31;

    // this warp's contiguous global chunk
    const int mwbase = blockIdx.x * M4_PER_BLOCK + w * M4_PER_WARP;
    const int cwbase = blockIdx.x * C4_PER_BLOCK + w * C4_PER_WARP;

    // ---- warp-coalesced async fill ----
#pragma unroll
    for (int k = 0; k < 3; k++)
        cpasync16(&smean[w * M4_PER_WARP + k * 32 + l],
                  &mean4[mwbase + k * 32 + l]);
#pragma unroll
    for (int k = 0; k < 9; k++)
        cpasync16(&scov[w * C4_PER_WARP + k * 32 + l],
                  &cov4[cwbase + k * 32 + l]);
    asm volatile("cp.async.commit_group;" ::: "memory");
    asm volatile("cp.async.wait_group 0;" ::: "memory");
    __syncwarp();

    // ---- per-thread compute on private smem region ----
    {
        float xm[12];
        float cv[36];

#pragma unroll
        for (int i = 0; i < 3; i++) {
            float4 v = smean[3 * t + i];
            xm[4 * i + 0] = v.x; xm[4 * i + 1] = v.y;
            xm[4 * i + 2] = v.z; xm[4 * i + 3] = v.w;
        }
#pragma unroll
        for (int i = 0; i < 9; i++) {
            float4 v = scov[9 * t + i];
            cv[4 * i + 0] = v.x; cv[4 * i + 1] = v.y;
            cv[4 * i + 2] = v.z; cv[4 * i + 3] = v.w;
        }

#pragma unroll
        for (int s = 0; s < 4; s++) {
            float x0 = xm[3 * s + 0];
            float x1 = xm[3 * s + 1];
            float x2 = xm[3 * s + 2];
            float* C = cv + 9 * s;

            float msq = x0 * x0 + x1 * x1 + x2 * x2;
            bool contract = (msq >= 1.0f);

            float inv = rsqrtf(msq);
            float gg = inv * (2.0f - inv);                      // (2m-1)/m^2
            float cc = 2.0f * inv * inv * inv * (inv - 1.0f);   // 2(1-m)/m^4

            xm[3 * s + 0] = contract ? gg * x0 : x0;
            xm[3 * s + 1] = contract ? gg * x1 : x1;
            xm[3 * s + 2] = contract ? gg * x2 : x2;

            // u = x^T C
            float u0 = x0 * C[0] + x1 * C[3] + x2 * C[6];
            float u1 = x0 * C[1] + x1 * C[4] + x2 * C[7];
            float u2 = x0 * C[2] + x1 * C[5] + x2 * C[8];

            // T = J*C = g*C + c*x u^T
            float T00 = gg * C[0] + cc * x0 * u0;
            float T01 = gg * C[1] + cc * x0 * u1;
            float T02 = gg * C[2] + cc * x0 * u2;
            float T10 = gg * C[3] + cc * x1 * u0;
            float T11 = gg * C[4] + cc * x1 * u1;
            float T12 = gg * C[5] + cc * x1 * u2;
            float T20 = gg * C[6] + cc * x2 * u0;
            float T21 = gg * C[7] + cc * x2 * u1;
            float T22 = gg * C[8] + cc * x2 * u2;

            // v = T x
            float v0 = T00 * x0 + T01 * x1 + T02 * x2;
            float v1 = T10 * x0 + T11 * x1 + T12 * x2;
            float v2 = T20 * x0 + T21 * x1 + T22 * x2;

            // O = g*T + c*v x^T  (J symmetric)
            C[0] = contract ? gg * T00 + cc * v0 * x0 : C[0];
            C[1] = contract ? gg * T01 + cc * v0 * x1 : C[1];
            C[2] = contract ? gg * T02 + cc * v0 * x2 : C[2];
            C[3] = contract ? gg * T10 + cc * v1 * x0 : C[3];
            C[4] = contract ? gg * T11 + cc * v1 * x1 : C[4];
            C[5] = contract ? gg * T12 + cc * v1 * x2 : C[5];
            C[6] = contract ? gg * T20 + cc * v2 * x0 : C[6];
            C[7] = contract ? gg * T21 + cc * v2 * x1 : C[7];
            C[8] = contract ? gg * T22 + cc * v2 * x2 : C[8];
        }

        // write back to private smem region (no cross-thread hazard)
#pragma unroll
        for (int i = 0; i < 3; i++)
            smean[3 * t + i] = make_float4(xm[4 * i + 0], xm[4 * i + 1],
                                           xm[4 * i + 2], xm[4 * i + 3]);
#pragma unroll
        for (int i = 0; i < 9; i++)
            scov[9 * t + i] = make_float4(cv[4 * i + 0], cv[4 * i + 1],
                                          cv[4 * i + 2], cv[4 * i + 3]);
    }
    __syncwarp();

    // ---- warp-coalesced drain ----
#pragma unroll
    for (int k = 0; k < 3; k++)
        mout4[mwbase + k * 32 + l] = smean[w * M4_PER_WARP + k * 32 + l];
#pragma unroll
    for (int k = 0; k < 9; k++)
        cout4[cwbase + k * 32 + l] = scov[w * C4_PER_WARP + k * 32 + l];
}

extern "C" void kernel_launch(void* const* d_in, const int* in_sizes, int n_in,
                              void* d_out, int out_size) {
    const float* mean = (const float*)d_in[0];   // [N,3]
    const float* cov  = (const float*)d_in[1];   // [N,3,3]
    float* out = (float*)d_out;                  // [N*3 means][N*9 cov]

    int N = in_sizes[0] / 3;                     // 4,194,304
    int ngroups = N / 4;                         // 1,048,576

    float4* mout4 = (float4*)out;
    float4* cout4 = (float4*)(out) + (size_t)3 * ngroups;

    int blocks = ngroups / THREADS;              // 8192, exact
    scene_contract_kernel<<<blocks, THREADS>>>(
        (const float4*)mean, (const float4*)cov, mout4, cout4);
}